// round 3
// baseline (speedup 1.0000x reference)
#include <cuda_runtime.h>

// Problem constants
// B=512, D=256, O=256, H=[512,1024,1024]
// out[b,o] = comp_b[b,o] + sum_d iv[b,d]*b_d[d*O+o]
//          + sum_{d,h} iv[b,d]*x3[b,h]*W_d[d*O+o, h]
// Main term computed as fused GEMM (M=512, N=256, K=256*1024) with A generated
// on the fly as iv[m,d]*x3[m,h]; split-K over d with deterministic reduction.

__device__ float g_x1[512 * 512];
__device__ float g_x2[512 * 1024];
__device__ float g_x3[512 * 1024];
__device__ float g_part[32 * 512 * 256];   // split-K partials [z][b][o]

// ---------------------------------------------------------------------------
// C[M,N] = relu(A[M,K] @ W[N,K]^T + bias[N])   (64x64 tile, 256 thr, 4x4/thr)
// ---------------------------------------------------------------------------
__global__ __launch_bounds__(256) void mlp_layer_kernel(
    const float* __restrict__ A, const float* __restrict__ W,
    const float* __restrict__ bias, float* __restrict__ C,
    int M, int N, int K)
{
    __shared__ float a_s[16][68];
    __shared__ float w_s[16][68];
    int m0 = blockIdx.y * 64, n0 = blockIdx.x * 64;
    int tid = threadIdx.x;
    int tx = tid & 15, ty = tid >> 4;
    int lrow = tid >> 2, lk = (tid & 3) * 4;
    float acc[4][4] = {};

    for (int k0 = 0; k0 < K; k0 += 16) {
        float4 av = *(const float4*)(A + (size_t)(m0 + lrow) * K + k0 + lk);
        float4 wv = *(const float4*)(W + (size_t)(n0 + lrow) * K + k0 + lk);
        a_s[lk + 0][lrow] = av.x; a_s[lk + 1][lrow] = av.y;
        a_s[lk + 2][lrow] = av.z; a_s[lk + 3][lrow] = av.w;
        w_s[lk + 0][lrow] = wv.x; w_s[lk + 1][lrow] = wv.y;
        w_s[lk + 2][lrow] = wv.z; w_s[lk + 3][lrow] = wv.w;
        __syncthreads();
        #pragma unroll
        for (int kk = 0; kk < 16; kk++) {
            float4 ra = *(const float4*)&a_s[kk][ty * 4];
            float4 rb = *(const float4*)&w_s[kk][tx * 4];
            float ar[4] = {ra.x, ra.y, ra.z, ra.w};
            float br[4] = {rb.x, rb.y, rb.z, rb.w};
            #pragma unroll
            for (int i = 0; i < 4; i++)
                #pragma unroll
                for (int j = 0; j < 4; j++)
                    acc[i][j] += ar[i] * br[j];
        }
        __syncthreads();
    }
    #pragma unroll
    for (int i = 0; i < 4; i++) {
        int m = m0 + ty * 4 + i;
        #pragma unroll
        for (int j = 0; j < 4; j++) {
            int n = n0 + tx * 4 + j;
            float v = acc[i][j] + bias[n];
            C[(size_t)m * N + n] = v > 0.f ? v : 0.f;
        }
    }
}

// ---------------------------------------------------------------------------
// out[b,o] = b_b[o] + sum_k x3[b,k]*W_b[o,k] + sum_d iv[b,d]*b_d[d*256+o]
// (64x64 tile; two K phases)
// ---------------------------------------------------------------------------
__global__ __launch_bounds__(256) void epi_init_kernel(
    const float* __restrict__ x3, const float* __restrict__ Wb,
    const float* __restrict__ bb, const float* __restrict__ iv,
    const float* __restrict__ bd, float* __restrict__ out)
{
    __shared__ float a_s[16][68];
    __shared__ float b_sm[16][68];
    int m0 = blockIdx.y * 64, n0 = blockIdx.x * 64;
    int tid = threadIdx.x;
    int tx = tid & 15, ty = tid >> 4;
    int lrow = tid >> 2, lk = (tid & 3) * 4;
    float acc[4][4] = {};

    // Phase 1: x3 @ Wb^T, K=1024 (Wb row-major [256,1024])
    for (int k0 = 0; k0 < 1024; k0 += 16) {
        float4 av = *(const float4*)(x3 + (size_t)(m0 + lrow) * 1024 + k0 + lk);
        float4 wv = *(const float4*)(Wb + (size_t)(n0 + lrow) * 1024 + k0 + lk);
        a_s[lk + 0][lrow] = av.x; a_s[lk + 1][lrow] = av.y;
        a_s[lk + 2][lrow] = av.z; a_s[lk + 3][lrow] = av.w;
        b_sm[lk + 0][lrow] = wv.x; b_sm[lk + 1][lrow] = wv.y;
        b_sm[lk + 2][lrow] = wv.z; b_sm[lk + 3][lrow] = wv.w;
        __syncthreads();
        #pragma unroll
        for (int kk = 0; kk < 16; kk++) {
            float4 ra = *(const float4*)&a_s[kk][ty * 4];
            float4 rb = *(const float4*)&b_sm[kk][tx * 4];
            float ar[4] = {ra.x, ra.y, ra.z, ra.w};
            float br[4] = {rb.x, rb.y, rb.z, rb.w};
            #pragma unroll
            for (int i = 0; i < 4; i++)
                #pragma unroll
                for (int j = 0; j < 4; j++)
                    acc[i][j] += ar[i] * br[j];
        }
        __syncthreads();
    }

    // Phase 2: iv @ bd  (bd viewed [K=256, N=256], n-contiguous)
    int lkk = tid >> 4, ln = (tid & 15) * 4;
    for (int k0 = 0; k0 < 256; k0 += 16) {
        float4 av = *(const float4*)(iv + (size_t)(m0 + lrow) * 256 + k0 + lk);
        a_s[lk + 0][lrow] = av.x; a_s[lk + 1][lrow] = av.y;
        a_s[lk + 2][lrow] = av.z; a_s[lk + 3][lrow] = av.w;
        float4 bv = *(const float4*)(bd + (size_t)(k0 + lkk) * 256 + n0 + ln);
        *(float4*)&b_sm[lkk][ln] = bv;
        __syncthreads();
        #pragma unroll
        for (int kk = 0; kk < 16; kk++) {
            float4 ra = *(const float4*)&a_s[kk][ty * 4];
            float4 rb = *(const float4*)&b_sm[kk][tx * 4];
            float ar[4] = {ra.x, ra.y, ra.z, ra.w};
            float br[4] = {rb.x, rb.y, rb.z, rb.w};
            #pragma unroll
            for (int i = 0; i < 4; i++)
                #pragma unroll
                for (int j = 0; j < 4; j++)
                    acc[i][j] += ar[i] * br[j];
        }
        __syncthreads();
    }

    #pragma unroll
    for (int i = 0; i < 4; i++) {
        int m = m0 + ty * 4 + i;
        #pragma unroll
        for (int j = 0; j < 4; j++) {
            int n = n0 + tx * 4 + j;
            out[(size_t)m * 256 + n] = acc[i][j] + bb[n];
        }
    }
}

// ---------------------------------------------------------------------------
// Main fused contraction. Grid (n=2, m=4, z=32). Each CTA: 128x128 output
// tile, 8 d-groups (K = 8*1024 = 8192). A tile generated as iv[m,d]*x3[m,h].
// Writes partials to g_part[z].
// ---------------------------------------------------------------------------
__global__ __launch_bounds__(256, 2) void main_fused_kernel(
    const float* __restrict__ iv, const float* __restrict__ x3,
    const float* __restrict__ Wd)
{
    __shared__ float a_s[16][132];
    __shared__ float b_s[16][132];
    __shared__ float ivs[128];
    int n0 = blockIdx.x * 128;
    int m0 = blockIdx.y * 128;
    int d0 = blockIdx.z * 8;
    int tid = threadIdx.x;
    int tx = tid & 15, ty = tid >> 4;
    int lrow = tid >> 2, lk = (tid & 3) * 4;
    float acc[8][8] = {};

    const float* Xp = x3 + (size_t)m0 * 1024;

    for (int dd = 0; dd < 8; dd++) {
        int d = d0 + dd;
        if (tid < 128) ivs[tid] = iv[(size_t)(m0 + tid) * 256 + d];
        __syncthreads();
        const float* Wp = Wd + (size_t)(d * 256 + n0) * 1024;

        for (int h0 = 0; h0 < 1024; h0 += 16) {
            #pragma unroll
            for (int r = 0; r < 2; r++) {
                int row = lrow + r * 64;
                float4 av = *(const float4*)(Xp + (size_t)row * 1024 + h0 + lk);
                float s = ivs[row];
                a_s[lk + 0][row] = av.x * s; a_s[lk + 1][row] = av.y * s;
                a_s[lk + 2][row] = av.z * s; a_s[lk + 3][row] = av.w * s;
                float4 bv = *(const float4*)(Wp + (size_t)row * 1024 + h0 + lk);
                b_s[lk + 0][row] = bv.x; b_s[lk + 1][row] = bv.y;
                b_s[lk + 2][row] = bv.z; b_s[lk + 3][row] = bv.w;
            }
            __syncthreads();
            #pragma unroll
            for (int kk = 0; kk < 16; kk++) {
                float ar[8], br[8];
                float4 t;
                t = *(const float4*)&a_s[kk][ty * 8];
                ar[0] = t.x; ar[1] = t.y; ar[2] = t.z; ar[3] = t.w;
                t = *(const float4*)&a_s[kk][ty * 8 + 4];
                ar[4] = t.x; ar[5] = t.y; ar[6] = t.z; ar[7] = t.w;
                t = *(const float4*)&b_s[kk][tx * 8];
                br[0] = t.x; br[1] = t.y; br[2] = t.z; br[3] = t.w;
                t = *(const float4*)&b_s[kk][tx * 8 + 4];
                br[4] = t.x; br[5] = t.y; br[6] = t.z; br[7] = t.w;
                #pragma unroll
                for (int i = 0; i < 8; i++)
                    #pragma unroll
                    for (int j = 0; j < 8; j++)
                        acc[i][j] += ar[i] * br[j];
            }
            __syncthreads();
        }
    }

    float* part = g_part + (size_t)blockIdx.z * 512 * 256;
    #pragma unroll
    for (int i = 0; i < 8; i++) {
        int m = m0 + ty * 8 + i;
        #pragma unroll
        for (int j = 0; j < 8; j++) {
            int n = n0 + tx * 8 + j;
            part[(size_t)m * 256 + n] = acc[i][j];
        }
    }
}

// ---------------------------------------------------------------------------
// Deterministic split-K reduction: out += sum_z part[z]
// ---------------------------------------------------------------------------
__global__ __launch_bounds__(256) void reduce_kernel(float* __restrict__ out)
{
    int idx = blockIdx.x * 256 + threadIdx.x;   // 0..131071
    float s = 0.f;
    #pragma unroll
    for (int z = 0; z < 32; z++)
        s += g_part[(size_t)z * 131072 + idx];
    out[idx] += s;
}

extern "C" void kernel_launch(void* const* d_in, const int* in_sizes, int n_in,
                              void* d_out, int out_size)
{
    const float* IV = (const float*)d_in[0];   // input_values [512,256]
    const float* NF = (const float*)d_in[1];   // nan_flag     [512,256]
    // `training` scalar may or may not be materialized as an input; detect.
    int base = (in_sizes[2] == 512 * 256) ? 2 : 3;
    const float* W_in = (const float*)d_in[base + 0];  // [512,256]
    const float* b_in = (const float*)d_in[base + 1];  // [512]
    const float* W_h1 = (const float*)d_in[base + 2];  // [1024,512]
    const float* b_h1 = (const float*)d_in[base + 3];  // [1024]
    const float* W_h2 = (const float*)d_in[base + 4];  // [1024,1024]
    const float* b_h2 = (const float*)d_in[base + 5];  // [1024]
    const float* W_d  = (const float*)d_in[base + 6];  // [65536,1024]
    const float* b_d  = (const float*)d_in[base + 7];  // [65536]
    const float* W_b  = (const float*)d_in[base + 8];  // [256,1024]
    const float* b_b  = (const float*)d_in[base + 9];  // [256]
    float* out = (float*)d_out;

    float *x1, *x2, *x3;
    cudaGetSymbolAddress((void**)&x1, g_x1);
    cudaGetSymbolAddress((void**)&x2, g_x2);
    cudaGetSymbolAddress((void**)&x3, g_x3);

    // MLP: x1 = relu(NF @ W_in^T + b_in), etc.
    mlp_layer_kernel<<<dim3(8, 8), 256>>>(NF, W_in, b_in, x1, 512, 512, 256);
    mlp_layer_kernel<<<dim3(16, 8), 256>>>(x1, W_h1, b_h1, x2, 512, 1024, 512);
    mlp_layer_kernel<<<dim3(16, 8), 256>>>(x2, W_h2, b_h2, x3, 512, 1024, 1024);

    // out = comp_b + iv@b_d-matrix  (bias/base terms)
    epi_init_kernel<<<dim3(4, 8), 256>>>(x3, W_b, b_b, IV, b_d, out);

    // Main fused contraction (split-K over d) + deterministic reduce
    main_fused_kernel<<<dim3(2, 4, 32), 256>>>(IV, x3, W_d);
    reduce_kernel<<<dim3(512), 256>>>(out);
}

// round 6
// speedup vs baseline: 2.1179x; 2.1179x over previous
#include <cuda_runtime.h>
#include <cuda_bf16.h>
#include <cstdint>

#define DINL __device__ __forceinline__

// B=512, D=256, O=256, H=[512,1024,1024]
// out[b,o] = b_b[o] + sum_h x3[b,h]*W_b[o,h] + sum_d iv[b,d]*b_d[d*256+o]
//          + sum_{d,h} iv[b,d]*x3[b,h]*W_d[d*256+o, h]
// Main + comp_b terms via warp-level bf16 mma.sync (hi/lo 3-GEMM split),
// split-K over d with deterministic reduction.

__device__ float g_x1[512 * 512];
__device__ float g_x2[512 * 1024];
__device__ float g_x3[512 * 1024];
__device__ float g_part[32 * 512 * 256];   // split-K partials [z][b][o]

DINL uint32_t s2u(const void* p) {
    uint32_t a;
    asm("{ .reg .u64 t; cvta.to.shared.u64 t, %1; cvt.u32.u64 %0, t; }"
        : "=r"(a) : "l"(p));
    return a;
}
// pack: low half = bf16(e0), high half = bf16(e1)
DINL uint32_t bfpack(float e0, float e1) {
    uint32_t r;
    asm("cvt.rn.bf16x2.f32 %0, %1, %2;" : "=r"(r) : "f"(e1), "f"(e0));
    return r;
}
DINL void ldsm4(uint32_t& r0, uint32_t& r1, uint32_t& r2, uint32_t& r3, uint32_t a) {
    asm volatile("ldmatrix.sync.aligned.m8n8.x4.shared.b16 {%0,%1,%2,%3}, [%4];"
                 : "=r"(r0), "=r"(r1), "=r"(r2), "=r"(r3) : "r"(a));
}
DINL void mma16816(float* c, const uint32_t* a, const uint32_t* b) {
    asm volatile(
        "mma.sync.aligned.m16n8k16.row.col.f32.bf16.bf16.f32 "
        "{%0,%1,%2,%3}, {%4,%5,%6,%7}, {%8,%9}, {%0,%1,%2,%3};"
        : "+f"(c[0]), "+f"(c[1]), "+f"(c[2]), "+f"(c[3])
        : "r"(a[0]), "r"(a[1]), "r"(a[2]), "r"(a[3]), "r"(b[0]), "r"(b[1]));
}

// smem layout (elements of bf16), row stride 24 (48B: ldmatrix conflict-free)
static constexpr int AS = 128 * 24;              // A tile (128 rows x 16 k)
static constexpr int BS = 256 * 24;              // B tile (256 rows x 16 k)
static constexpr int BUF_EL = 2 * AS + 2 * BS;   // Ahi|Alo|Bhi|Blo = 18432 el
static constexpr int OAHI = 0, OALO = AS, OBHI = 2 * AS, OBLO = 2 * AS + BS;
static constexpr int DSMEM_BYTES = 2 * BUF_EL * 2;   // 73728 B

// ---------------------------------------------------------------------------
// Main fused contraction on warp MMA. Grid (m=4, z=32), 512 threads.
// CTA output tile 128x256 fp32 in regs; K = 8*1024 (+1024 Wb fold at z==0).
// ---------------------------------------------------------------------------
__global__ __launch_bounds__(512) void main_mma_kernel(
    const float* __restrict__ iv, const float* __restrict__ Wd,
    const float* __restrict__ Wb, const float* __restrict__ x3)
{
    extern __shared__ __align__(16) __nv_bfloat16 sm[];
    const int tid = threadIdx.x, lane = tid & 31, wid = tid >> 5;
    const int m0 = blockIdx.x * 128, z = blockIdx.y;
    const int wm = (wid & 1) * 64, wn = (wid >> 1) * 32;
    const int nst = (z == 0) ? 9 * 64 : 8 * 64;

    // load roles: A-gen 4 threads/row, B 2 threads/row (64B contiguous per row)
    const int rowA = tid >> 2, k4 = (tid & 3) * 4;
    const int rowB = tid >> 1, k8 = (tid & 1) * 8;

    float acc[4][4][4] = {};   // [mi][ni][frag]

    float4 aF, b0F, b1F;
    float ivv;
    auto ldg_stage = [&](int s) {
        int g = s >> 6, h0 = (s & 63) * 16;
        const float* Wbase = (g < 8) ? (Wd + ((size_t)(z * 8 + g) * 256) * 1024) : Wb;
        ivv = (g < 8) ? __ldg(iv + (size_t)(m0 + rowA) * 256 + (z * 8 + g)) : 1.0f;
        aF = *(const float4*)(x3 + (size_t)(m0 + rowA) * 1024 + h0 + k4);
        const float* wp = Wbase + (size_t)rowB * 1024 + h0 + k8;
        b0F = *(const float4*)(wp);
        b1F = *(const float4*)(wp + 4);
    };
    ldg_stage(0);

    const uint32_t smu = s2u(sm);
    // ldmatrix per-lane addresses (element offsets within a tile)
    const int arow = (lane & 7) + ((lane >> 3) & 1) * 8;   // A: row8 bit = l>>3
    const int akh = ((lane >> 4) & 1) * 8;                 // A: k-half = l>>4
    const int brow = (lane & 7) + ((lane >> 4) & 1) * 8;   // B: row8 bit = l>>4
    const int bkh = ((lane >> 3) & 1) * 8;                 // B: k-half = l>>3

    for (int s = 0; s < nst; ++s) {
        const int buf = s & 1;
        __nv_bfloat16* bp = sm + buf * BUF_EL;

        // ---- convert + STS stage s (A = iv*x3; hi/lo bf16 split) ----
        {
            float fx = aF.x * ivv, fy = aF.y * ivv, fz = aF.z * ivv, fw = aF.w * ivv;
            uint32_t h01 = bfpack(fx, fy), h23 = bfpack(fz, fw);
            float hx = __uint_as_float(h01 << 16);
            float hy = __uint_as_float(h01 & 0xFFFF0000u);
            float hz = __uint_as_float(h23 << 16);
            float hw = __uint_as_float(h23 & 0xFFFF0000u);
            uint32_t l01 = bfpack(fx - hx, fy - hy), l23 = bfpack(fz - hz, fw - hw);
            *(uint2*)(bp + OAHI + rowA * 24 + k4) = make_uint2(h01, h23);
            *(uint2*)(bp + OALO + rowA * 24 + k4) = make_uint2(l01, l23);

            uint32_t p01 = bfpack(b0F.x, b0F.y), p23 = bfpack(b0F.z, b0F.w);
            float px = __uint_as_float(p01 << 16);
            float py = __uint_as_float(p01 & 0xFFFF0000u);
            float pz = __uint_as_float(p23 << 16);
            float pw = __uint_as_float(p23 & 0xFFFF0000u);
            uint32_t q01 = bfpack(b0F.x - px, b0F.y - py);
            uint32_t q23 = bfpack(b0F.z - pz, b0F.w - pw);
            *(uint2*)(bp + OBHI + rowB * 24 + k8) = make_uint2(p01, p23);
            *(uint2*)(bp + OBLO + rowB * 24 + k8) = make_uint2(q01, q23);

            uint32_t r01 = bfpack(b1F.x, b1F.y), r23 = bfpack(b1F.z, b1F.w);
            float rx = __uint_as_float(r01 << 16);
            float ry = __uint_as_float(r01 & 0xFFFF0000u);
            float rz = __uint_as_float(r23 << 16);
            float rw = __uint_as_float(r23 & 0xFFFF0000u);
            uint32_t s01 = bfpack(b1F.x - rx, b1F.y - ry);
            uint32_t s23 = bfpack(b1F.z - rz, b1F.w - rw);
            *(uint2*)(bp + OBHI + rowB * 24 + k8 + 4) = make_uint2(r01, r23);
            *(uint2*)(bp + OBLO + rowB * 24 + k8 + 4) = make_uint2(s01, s23);
        }
        __syncthreads();

        // prefetch next stage's gmem while MMAs run
        if (s + 1 < nst) ldg_stage(s + 1);

        // ---- ldmatrix + 48 mma (Ahi*Bhi, Ahi*Blo, Alo*Bhi) ----
        const uint32_t base = smu + (uint32_t)buf * (BUF_EL * 2);
        uint32_t Ah[4][4], Bh[2][4], Bl[2][4];
        #pragma unroll
        for (int t = 0; t < 4; t++)
            ldsm4(Ah[t][0], Ah[t][1], Ah[t][2], Ah[t][3],
                  base + (uint32_t)(OAHI + (wm + t * 16 + arow) * 24 + akh) * 2);
        #pragma unroll
        for (int p = 0; p < 2; p++) {
            ldsm4(Bh[p][0], Bh[p][1], Bh[p][2], Bh[p][3],
                  base + (uint32_t)(OBHI + (wn + p * 16 + brow) * 24 + bkh) * 2);
            ldsm4(Bl[p][0], Bl[p][1], Bl[p][2], Bl[p][3],
                  base + (uint32_t)(OBLO + (wn + p * 16 + brow) * 24 + bkh) * 2);
        }
        #pragma unroll
        for (int mi = 0; mi < 4; mi++)
            #pragma unroll
            for (int ni = 0; ni < 4; ni++) {
                mma16816(acc[mi][ni], Ah[mi], &Bh[ni >> 1][(ni & 1) * 2]);
                mma16816(acc[mi][ni], Ah[mi], &Bl[ni >> 1][(ni & 1) * 2]);
            }
        uint32_t Al[4][4];
        #pragma unroll
        for (int t = 0; t < 4; t++)
            ldsm4(Al[t][0], Al[t][1], Al[t][2], Al[t][3],
                  base + (uint32_t)(OALO + (wm + t * 16 + arow) * 24 + akh) * 2);
        #pragma unroll
        for (int mi = 0; mi < 4; mi++)
            #pragma unroll
            for (int ni = 0; ni < 4; ni++)
                mma16816(acc[mi][ni], Al[mi], &Bh[ni >> 1][(ni & 1) * 2]);
    }

    // ---- epilogue: write split-K partials ----
    float* part = g_part + (size_t)z * (512 * 256);
    #pragma unroll
    for (int mi = 0; mi < 4; mi++) {
        int mr = m0 + wm + mi * 16 + (lane >> 2);
        #pragma unroll
        for (int ni = 0; ni < 4; ni++) {
            int nc = wn + ni * 8 + (lane & 3) * 2;
            *(float2*)(part + (size_t)mr * 256 + nc) =
                make_float2(acc[mi][ni][0], acc[mi][ni][1]);
            *(float2*)(part + (size_t)(mr + 8) * 256 + nc) =
                make_float2(acc[mi][ni][2], acc[mi][ni][3]);
        }
    }
}

// ---------------------------------------------------------------------------
// MLP layer: C = relu(A @ W^T + bias)   (fp32 SIMT; next-round target)
// ---------------------------------------------------------------------------
__global__ __launch_bounds__(256) void mlp_layer_kernel(
    const float* __restrict__ A, const float* __restrict__ W,
    const float* __restrict__ bias, float* __restrict__ C,
    int M, int N, int K)
{
    __shared__ float a_s[16][68];
    __shared__ float w_s[16][68];
    int m0 = blockIdx.y * 64, n0 = blockIdx.x * 64;
    int tid = threadIdx.x;
    int tx = tid & 15, ty = tid >> 4;
    int lrow = tid >> 2, lk = (tid & 3) * 4;
    float acc[4][4] = {};

    for (int k0 = 0; k0 < K; k0 += 16) {
        float4 av = *(const float4*)(A + (size_t)(m0 + lrow) * K + k0 + lk);
        float4 wv = *(const float4*)(W + (size_t)(n0 + lrow) * K + k0 + lk);
        a_s[lk + 0][lrow] = av.x; a_s[lk + 1][lrow] = av.y;
        a_s[lk + 2][lrow] = av.z; a_s[lk + 3][lrow] = av.w;
        w_s[lk + 0][lrow] = wv.x; w_s[lk + 1][lrow] = wv.y;
        w_s[lk + 2][lrow] = wv.z; w_s[lk + 3][lrow] = wv.w;
        __syncthreads();
        #pragma unroll
        for (int kk = 0; kk < 16; kk++) {
            float4 ra = *(const float4*)&a_s[kk][ty * 4];
            float4 rb = *(const float4*)&w_s[kk][tx * 4];
            float ar[4] = {ra.x, ra.y, ra.z, ra.w};
            float br[4] = {rb.x, rb.y, rb.z, rb.w};
            #pragma unroll
            for (int i = 0; i < 4; i++)
                #pragma unroll
                for (int j = 0; j < 4; j++)
                    acc[i][j] += ar[i] * br[j];
        }
        __syncthreads();
    }
    #pragma unroll
    for (int i = 0; i < 4; i++) {
        int m = m0 + ty * 4 + i;
        #pragma unroll
        for (int j = 0; j < 4; j++) {
            int n = n0 + tx * 4 + j;
            float v = acc[i][j] + bias[n];
            C[(size_t)m * N + n] = v > 0.f ? v : 0.f;
        }
    }
}

// ---------------------------------------------------------------------------
// out[b,o] = b_b[o] + sum_z part[z][b,o] + sum_d iv[b,d]*b_d[d*256+o]
// ---------------------------------------------------------------------------
__global__ __launch_bounds__(256) void reduce_kernel(
    const float* __restrict__ iv, const float* __restrict__ bd,
    const float* __restrict__ bb, float* __restrict__ out)
{
    __shared__ float sIv[256];
    int b = blockIdx.x;
    int o = threadIdx.x;
    sIv[o] = iv[(size_t)b * 256 + o];
    __syncthreads();
    size_t idx = (size_t)b * 256 + o;
    float s = bb[o];
    #pragma unroll 8
    for (int z = 0; z < 32; z++)
        s += g_part[(size_t)z * 131072 + idx];
    #pragma unroll 8
    for (int d = 0; d < 256; d++)
        s = fmaf(sIv[d], bd[d * 256 + o], s);
    out[idx] = s;
}

extern "C" void kernel_launch(void* const* d_in, const int* in_sizes, int n_in,
                              void* d_out, int out_size)
{
    const float* IV = (const float*)d_in[0];   // input_values [512,256]
    const float* NF = (const float*)d_in[1];   // nan_flag     [512,256]
    int base = (in_sizes[2] == 512 * 256) ? 2 : 3;   // skip `training` if present
    const float* W_in = (const float*)d_in[base + 0];  // [512,256]
    const float* b_in = (const float*)d_in[base + 1];  // [512]
    const float* W_h1 = (const float*)d_in[base + 2];  // [1024,512]
    const float* b_h1 = (const float*)d_in[base + 3];  // [1024]
    const float* W_h2 = (const float*)d_in[base + 4];  // [1024,1024]
    const float* b_h2 = (const float*)d_in[base + 5];  // [1024]
    const float* W_d  = (const float*)d_in[base + 6];  // [65536,1024]
    const float* b_d  = (const float*)d_in[base + 7];  // [65536]
    const float* W_b  = (const float*)d_in[base + 8];  // [256,1024]
    const float* b_b  = (const float*)d_in[base + 9];  // [256]
    float* out = (float*)d_out;

    float *x1, *x2, *x3;
    cudaGetSymbolAddress((void**)&x1, g_x1);
    cudaGetSymbolAddress((void**)&x2, g_x2);
    cudaGetSymbolAddress((void**)&x3, g_x3);

    cudaFuncSetAttribute(main_mma_kernel,
                         cudaFuncAttributeMaxDynamicSharedMemorySize, DSMEM_BYTES);

    // MLP
    mlp_layer_kernel<<<dim3(8, 8), 256>>>(NF, W_in, b_in, x1, 512, 512, 256);
    mlp_layer_kernel<<<dim3(16, 8), 256>>>(x1, W_h1, b_h1, x2, 512, 1024, 512);
    mlp_layer_kernel<<<dim3(16, 8), 256>>>(x2, W_h2, b_h2, x3, 512, 1024, 1024);

    // Main contraction (+ W_b fold at z==0) on warp MMA
    main_mma_kernel<<<dim3(4, 32), 512, DSMEM_BYTES>>>(IV, W_d, W_b, x3);

    // Deterministic split-K reduce + bias terms
    reduce_kernel<<<dim3(512), 256>>>(IV, b_d, b_b, out);
}